// round 6
// baseline (speedup 1.0000x reference)
#include <cuda_runtime.h>
#include <math.h>

#define BB    256
#define AA    512
#define DDW   64
#define NPOS  (AA*DDW)
#define NTH   256
#define CH    8
#define ROWS  (AA/CH)
#define EPSF  1e-5f
#define FULLM 0xffffffffu

typedef unsigned long long u64x;   // packed f32x2: (lo = pos d=lane, hi = pos d=lane+32)

__device__ float  g_x1[(size_t)BB*NPOS*4];
__device__ float  g_x2[(size_t)BB*NPOS*4];
__device__ float  g_z [(size_t)BB*AA*16];
__device__ float2 g_p1[BB*CH], g_p2[BB*CH], g_p3[BB*CH], g_p4[BB*CH];

// ---------- packed f32x2 primitives ----------
__device__ __forceinline__ u64x pk2(float a, float b){
  u64x r; asm("mov.b64 %0,{%1,%2};" : "=l"(r) : "f"(a), "f"(b)); return r;
}
__device__ __forceinline__ void up2(u64x v, float& a, float& b){
  asm("mov.b64 {%0,%1},%2;" : "=f"(a), "=f"(b) : "l"(v));
}
__device__ __forceinline__ u64x fma2_(u64x a, u64x b, u64x c){
  u64x d; asm("fma.rn.f32x2 %0,%1,%2,%3;" : "=l"(d) : "l"(a), "l"(b), "l"(c)); return d;
}
__device__ __forceinline__ u64x add2_(u64x a, u64x b){
  u64x d; asm("add.rn.f32x2 %0,%1,%2;" : "=l"(d) : "l"(a), "l"(b)); return d;
}
__device__ __forceinline__ u64x mul2_(u64x a, u64x b){
  u64x d; asm("mul.rn.f32x2 %0,%1,%2;" : "=l"(d) : "l"(a), "l"(b)); return d;
}

__device__ __forceinline__ float4 f4add(float4 a, float4 b){
  return make_float4(a.x+b.x, a.y+b.y, a.z+b.z, a.w+b.w);
}
__device__ __forceinline__ float geluf(float x){
  return 0.5f * x * (1.f + erff(x * 0.70710678118654752440f));
}
__device__ __forceinline__ u64x gelu2(u64x v){
  float a, b; up2(v, a, b);
  return pk2(geluf(a), geluf(b));
}
__device__ __forceinline__ void pack4(const float4& A, const float4& B, u64x C[4]){
  C[0] = pk2(A.x, B.x); C[1] = pk2(A.y, B.y); C[2] = pk2(A.z, B.z); C[3] = pk2(A.w, B.w);
}

// taps for outputs d=lane (lo) and d=lane+32 (hi); inputs T0=v(lane), T1=v(lane+32)
__device__ __forceinline__ void makeTapsP(const float4& T0, const float4& T1, int lane,
                                          u64x M[4], u64x P[4]){
  const float* a = reinterpret_cast<const float*>(&T0);
  const float* b = reinterpret_cast<const float*>(&T1);
  const int lm = (lane-2)&31, lp = (lane+2)&31;
  const bool lofix = lane < 2, hifix = lane >= 30;
  #pragma unroll
  for (int c = 0; c < 4; c++){
    float ml = __shfl_sync(FULLM, a[c], lm);
    float mh = __shfl_sync(FULLM, b[c], lm);
    M[c] = lofix ? pk2(0.f, ml) : pk2(ml, mh);
    float pl = __shfl_sync(FULLM, a[c], lp);
    float ph = __shfl_sync(FULLM, b[c], lp);
    P[c] = hifix ? pk2(ph, 0.f) : pk2(pl, ph);
  }
}

// packed dilated conv, output channel o; W layout [(k*4+o)*4+c], broadcast pairs
__device__ __forceinline__ u64x convO(const u64x* __restrict__ W, int o,
                                      const u64x M[4], const u64x C[4], const u64x P[4]){
  const u64x* w0 = W + o*4;
  const u64x* w1 = W + (4+o)*4;
  const u64x* w2 = W + (8+o)*4;
  u64x acc = mul2_(w0[0], M[0]);
  acc = fma2_(w0[1], M[1], acc);
  acc = fma2_(w0[2], M[2], acc);
  acc = fma2_(w0[3], M[3], acc);
  acc = fma2_(w1[0], C[0], acc);
  acc = fma2_(w1[1], C[1], acc);
  acc = fma2_(w1[2], C[2], acc);
  acc = fma2_(w1[3], C[3], acc);
  acc = fma2_(w2[0], P[0], acc);
  acc = fma2_(w2[1], P[1], acc);
  acc = fma2_(w2[2], P[2], acc);
  acc = fma2_(w2[3], P[3], acc);
  return acc;
}
__device__ __forceinline__ u64x pwO(const u64x* __restrict__ PW, int o, const u64x t[4]){
  u64x acc = mul2_(PW[o*4+0], t[0]);
  acc = fma2_(PW[o*4+1], t[1], acc);
  acc = fma2_(PW[o*4+2], t[2], acc);
  acc = fma2_(PW[o*4+3], t[3], acc);
  return acc;
}
// SMEM packers (call with tid)
__device__ __forceinline__ void packConvW(int tid, const float* __restrict__ wp, u64x* shW){
  if (tid < 48){
    int c = tid & 3, o = (tid >> 2) & 3, k = tid >> 4;
    float w = wp[o*12 + c*3 + k];
    shW[(k*4+o)*4+c] = pk2(w, w);
  }
}
__device__ __forceinline__ void packPwW(int tid, const float* __restrict__ wp, u64x* shPW){
  if (tid < 16){ float w = wp[tid]; shPW[tid] = pk2(w, w); }
}

__device__ __forceinline__ void blockReduceStore(float s, float q, float2* dst){
  #pragma unroll
  for (int off = 16; off > 0; off >>= 1){
    s += __shfl_xor_sync(FULLM, s, off);
    q += __shfl_xor_sync(FULLM, q, off);
  }
  __shared__ float red[16];
  int wp = threadIdx.x >> 5, ln = threadIdx.x & 31;
  if (ln == 0){ red[wp] = s; red[8+wp] = q; }
  __syncthreads();
  if (threadIdx.x == 0){
    float ss = 0.f, qq = 0.f;
    #pragma unroll
    for (int i = 0; i < 8; i++){ ss += red[i]; qq += red[8+i]; }
    *dst = make_float2(ss, qq);
  }
}
__device__ __forceinline__ void finalizeStats(const float2* __restrict__ part, int b,
                                              float invN, float& m, float& inv){
  float s = 0.f, q = 0.f;
  #pragma unroll
  for (int i = 0; i < CH; i++){
    float2 p = __ldg(&part[b*CH + i]);
    s += p.x; q += p.y;
  }
  m = s*invN;
  inv = rsqrtf(fmaf(-m, m, q*invN) + EPSF);
}
__device__ __forceinline__ void blockReduce2(float& s, float& q, volatile float* red){
  #pragma unroll
  for (int off = 16; off > 0; off >>= 1){
    s += __shfl_xor_sync(FULLM, s, off);
    q += __shfl_xor_sync(FULLM, q, off);
  }
  int wp = threadIdx.x >> 5, ln = threadIdx.x & 31;
  __syncthreads();
  if (ln == 0){ red[wp] = s; red[8+wp] = q; }
  __syncthreads();
  if (threadIdx.x == 0){
    float ss = 0.f, qq = 0.f;
    #pragma unroll
    for (int i = 0; i < 8; i++){ ss += red[i]; qq += red[8+i]; }
    red[16] = ss; red[17] = qq;
  }
  __syncthreads();
  s = red[16]; q = red[17];
}

#define INV_N1  (1.f/(4.f*(float)NPOS))
#define INV_N12 (1.f/(12.f*(float)NPOS))

// ============ K0: stats of y1 = conv1(s) ============
__global__ void __launch_bounds__(NTH, 3)
k_statsA(const float* __restrict__ s, const float* __restrict__ d1w1)
{
  __shared__ u64x shW[48];
  const int b = blockIdx.x >> 3, chk = blockIdx.x & 7, tid = threadIdx.x;
  const int lane = tid & 31, warp = tid >> 5;
  packConvW(tid, d1w1, shW);
  __syncthreads();
  const float4* sb = reinterpret_cast<const float4*>(
      s + (size_t)b*NPOS*4 + (size_t)chk*ROWS*DDW*4);
  u64x sum2 = 0ULL, sq2 = 0ULL;
  for (int r = 0; r < 8; ++r){
    int a = warp + 8*r;
    float4 T0 = sb[a*DDW + lane], T1 = sb[a*DDW + lane + 32];
    u64x C[4], M[4], P[4];
    pack4(T0, T1, C);
    makeTapsP(T0, T1, lane, M, P);
    #pragma unroll
    for (int o = 0; o < 4; o++){
      u64x y = convO(shW, o, M, C, P);
      sum2 = add2_(sum2, y);
      sq2  = fma2_(y, y, sq2);
    }
  }
  float sa, sb2, qa, qb;
  up2(sum2, sa, sb2); up2(sq2, qa, qb);
  blockReduceStore(sa + sb2, qa + qb, &g_p1[blockIdx.x]);
}

// ============ K1: x1 = gelu(pw1(LN(y1))); write x1; stats of y2 = conv2(s+x1) ============
__global__ void __launch_bounds__(NTH, 3)
k_passB(const float* __restrict__ s, const float* __restrict__ d1w1,
        const float* __restrict__ d1w2, const float* __restrict__ d2w1)
{
  __shared__ u64x shW1[48], shW2[48], shP1[16];
  const int b = blockIdx.x >> 3, chk = blockIdx.x & 7, tid = threadIdx.x;
  const int lane = tid & 31, warp = tid >> 5;
  const size_t off = (size_t)b*NPOS*4 + (size_t)chk*ROWS*DDW*4;
  const float4* sb  = reinterpret_cast<const float4*>(s + off);
  float4*       x1b = reinterpret_cast<float4*>(g_x1 + off);
  packConvW(tid, d1w1, shW1);
  packConvW(tid, d2w1, shW2);
  packPwW(tid, d1w2, shP1);
  float m1, i1; finalizeStats(g_p1, b, INV_N1, m1, i1);
  const u64x ii1 = pk2(i1, i1), mm1 = pk2(-m1*i1, -m1*i1);
  __syncthreads();

  u64x sum2 = 0ULL, sq2 = 0ULL;
  for (int r = 0; r < 8; ++r){
    int a = warp + 8*r;
    float4 T0 = sb[a*DDW + lane], T1 = sb[a*DDW + lane + 32];
    u64x C[4], M[4], P[4];
    pack4(T0, T1, C);
    makeTapsP(T0, T1, lane, M, P);
    u64x t[4];
    #pragma unroll
    for (int o = 0; o < 4; o++)
      t[o] = fma2_(convO(shW1, o, M, C, P), ii1, mm1);
    u64x x[4];
    #pragma unroll
    for (int o = 0; o < 4; o++) x[o] = gelu2(pwO(shP1, o, t));
    float xa[4], xb[4];
    #pragma unroll
    for (int o = 0; o < 4; o++) up2(x[o], xa[o], xb[o]);
    float4 xv0 = make_float4(xa[0], xa[1], xa[2], xa[3]);
    float4 xv1 = make_float4(xb[0], xb[1], xb[2], xb[3]);
    x1b[a*DDW + lane]      = xv0;
    x1b[a*DDW + lane + 32] = xv1;
    u64x XM[4], XP[4];
    makeTapsP(xv0, xv1, lane, XM, XP);
    #pragma unroll
    for (int c = 0; c < 4; c++){
      M[c] = add2_(M[c], XM[c]);
      C[c] = add2_(C[c], x[c]);
      P[c] = add2_(P[c], XP[c]);
    }
    #pragma unroll
    for (int o = 0; o < 4; o++){
      u64x y = convO(shW2, o, M, C, P);
      sum2 = add2_(sum2, y);
      sq2  = fma2_(y, y, sq2);
    }
  }
  float sa, sb2, qa, qb;
  up2(sum2, sa, sb2); up2(sq2, qa, qb);
  blockReduceStore(sa + sb2, qa + qb, &g_p2[blockIdx.x]);
}

// ============ K2: x2; write x2; stats of y3 = conv3(s+x1+x2) ============
__global__ void __launch_bounds__(NTH, 3)
k_passC(const float* __restrict__ s, const float* __restrict__ d2w1,
        const float* __restrict__ d2w2, const float* __restrict__ d3w1)
{
  __shared__ u64x shW2[48], shW3[48], shP2[16];
  const int b = blockIdx.x >> 3, chk = blockIdx.x & 7, tid = threadIdx.x;
  const int lane = tid & 31, warp = tid >> 5;
  const size_t off = (size_t)b*NPOS*4 + (size_t)chk*ROWS*DDW*4;
  const float4* sb  = reinterpret_cast<const float4*>(s + off);
  const float4* x1b = reinterpret_cast<const float4*>(g_x1 + off);
  float4*       x2b = reinterpret_cast<float4*>(g_x2 + off);
  packConvW(tid, d2w1, shW2);
  packConvW(tid, d3w1, shW3);
  packPwW(tid, d2w2, shP2);
  float m2, i2; finalizeStats(g_p2, b, INV_N1, m2, i2);
  const u64x ii2 = pk2(i2, i2), mm2 = pk2(-m2*i2, -m2*i2);
  __syncthreads();

  u64x sum2 = 0ULL, sq2 = 0ULL;
  for (int r = 0; r < 8; ++r){
    int a = warp + 8*r;
    float4 I0 = f4add(sb[a*DDW + lane],      x1b[a*DDW + lane]);
    float4 I1 = f4add(sb[a*DDW + lane + 32], x1b[a*DDW + lane + 32]);
    u64x C[4], M[4], P[4];
    pack4(I0, I1, C);
    makeTapsP(I0, I1, lane, M, P);
    u64x t[4];
    #pragma unroll
    for (int o = 0; o < 4; o++)
      t[o] = fma2_(convO(shW2, o, M, C, P), ii2, mm2);
    u64x x[4];
    #pragma unroll
    for (int o = 0; o < 4; o++) x[o] = gelu2(pwO(shP2, o, t));
    float xa[4], xb[4];
    #pragma unroll
    for (int o = 0; o < 4; o++) up2(x[o], xa[o], xb[o]);
    float4 xv0 = make_float4(xa[0], xa[1], xa[2], xa[3]);
    float4 xv1 = make_float4(xb[0], xb[1], xb[2], xb[3]);
    x2b[a*DDW + lane]      = xv0;
    x2b[a*DDW + lane + 32] = xv1;
    u64x XM[4], XP[4];
    makeTapsP(xv0, xv1, lane, XM, XP);
    #pragma unroll
    for (int c = 0; c < 4; c++){
      M[c] = add2_(M[c], XM[c]);
      C[c] = add2_(C[c], x[c]);
      P[c] = add2_(P[c], XP[c]);
    }
    #pragma unroll
    for (int o = 0; o < 4; o++){
      u64x y = convO(shW3, o, M, C, P);
      sum2 = add2_(sum2, y);
      sq2  = fma2_(y, y, sq2);
    }
  }
  float sa, sb2, qa, qb;
  up2(sum2, sa, sb2); up2(sq2, qa, qb);
  blockReduceStore(sa + sb2, qa + qb, &g_p3[blockIdx.x]);
}

// ============ K3: x3 (regs) + zraw + cat stats, packed ============
__global__ void __launch_bounds__(NTH, 2)
k_passD(const float* __restrict__ s, const float* __restrict__ d3w1,
        const float* __restrict__ d3w2, const float* __restrict__ cw,
        const float* __restrict__ c2w)
{
  __shared__ u64x sh_c2[16*4*32];     // [(o*4+p)*32 + lane] = (c2w[d=lane], c2w[d=lane+32])
  __shared__ u64x shCW[48];           // cw broadcast pairs [p*12+c]
  __shared__ u64x shW3[48], shP3[16];
  const int b = blockIdx.x >> 3, chk = blockIdx.x & 7, tid = threadIdx.x;
  const int lane = tid & 31, warp = tid >> 5;
  const size_t off = (size_t)b*NPOS*4 + (size_t)chk*ROWS*DDW*4;
  const float4* sb  = reinterpret_cast<const float4*>(s + off);
  const float4* x1b = reinterpret_cast<const float4*>(g_x1 + off);
  const float4* x2b = reinterpret_cast<const float4*>(g_x2 + off);
  for (int k = tid; k < 2048; k += NTH){
    int l = k & 31, p = (k >> 5) & 3, o = k >> 7;
    sh_c2[k] = pk2(c2w[o*256 + p*64 + l], c2w[o*256 + p*64 + l + 32]);
  }
  if (tid < 48){ float w = cw[tid]; shCW[tid] = pk2(w, w); }
  packConvW(tid, d3w1, shW3);
  packPwW(tid, d3w2, shP3);
  float m3, i3; finalizeStats(g_p3, b, INV_N1, m3, i3);
  const u64x ii3 = pk2(i3, i3), mm3 = pk2(-m3*i3, -m3*i3);
  __syncthreads();

  u64x sum2 = 0ULL, sq2 = 0ULL;
  for (int g = 0; g < 2; ++g){
    u64x V[4][4];                      // [row][p] packed position pairs
    // -------- phase 1 --------
    #pragma unroll
    for (int r = 0; r < 4; ++r){
      int a = warp + 8*(4*g + r);
      float4 X0 = x1b[a*DDW + lane], X1 = x1b[a*DDW + lane + 32];
      float4 Y0 = x2b[a*DDW + lane], Y1 = x2b[a*DDW + lane + 32];
      float4 I0 = f4add(f4add(sb[a*DDW + lane],      X0), Y0);
      float4 I1 = f4add(f4add(sb[a*DDW + lane + 32], X1), Y1);
      u64x IC[4], M[4], P[4];
      pack4(I0, I1, IC);
      makeTapsP(I0, I1, lane, M, P);
      u64x t[4];
      #pragma unroll
      for (int o = 0; o < 4; o++)
        t[o] = fma2_(convO(shW3, o, M, IC, P), ii3, mm3);
      u64x cat[12];                    // x1(0..3), x2(4..7), x3(8..11) packed
      pack4(X0, X1, cat);
      pack4(Y0, Y1, cat + 4);
      #pragma unroll
      for (int o = 0; o < 4; o++) cat[8+o] = gelu2(pwO(shP3, o, t));
      #pragma unroll
      for (int c = 0; c < 12; c++){
        sum2 = add2_(sum2, cat[c]);
        sq2  = fma2_(cat[c], cat[c], sq2);
      }
      #pragma unroll
      for (int p = 0; p < 4; p++){
        u64x acc = mul2_(shCW[p*12], cat[0]);
        #pragma unroll
        for (int c = 1; c < 12; c++)
          acc = fma2_(shCW[p*12+c], cat[c], acc);
        V[r][p] = acc;
      }
    }
    // -------- phase 2: z[o]; c2w read once per o --------
    #pragma unroll
    for (int o = 0; o < 16; ++o){
      u64x wv[4];
      #pragma unroll
      for (int p = 0; p < 4; p++)
        wv[p] = sh_c2[(o*4 + p)*32 + lane];
      float acc[4];
      #pragma unroll
      for (int r = 0; r < 4; ++r){
        u64x a2 = mul2_(wv[0], V[r][0]);
        a2 = fma2_(wv[1], V[r][1], a2);
        a2 = fma2_(wv[2], V[r][2], a2);
        a2 = fma2_(wv[3], V[r][3], a2);
        float l0, h0; up2(a2, l0, h0);
        acc[r] = l0 + h0;
      }
      const bool b4 = (lane & 16) != 0, b3 = (lane & 8) != 0;
      float s0 = b4 ? acc[2] : acc[0];
      float s1 = b4 ? acc[3] : acc[1];
      s0 += __shfl_xor_sync(FULLM, b4 ? acc[0] : acc[2], 16);
      s1 += __shfl_xor_sync(FULLM, b4 ? acc[1] : acc[3], 16);
      float sv = b3 ? s1 : s0;
      sv += __shfl_xor_sync(FULLM, b3 ? s0 : s1, 8);
      sv += __shfl_xor_sync(FULLM, sv, 4);
      sv += __shfl_xor_sync(FULLM, sv, 2);
      sv += __shfl_xor_sync(FULLM, sv, 1);
      if ((lane & 7) == 0){
        int r = ((lane >> 4) << 1) | ((lane >> 3) & 1);
        int ag = chk*ROWS + warp + 8*(4*g + r);
        g_z[((size_t)b*AA + ag)*16 + o] = sv;
      }
    }
  }
  float sa, sb2, qa, qb;
  up2(sum2, sa, sb2); up2(sq2, qa, qb);
  blockReduceStore(sa + sb2, qa + qb, &g_p4[blockIdx.x]);
}

// ============ K4: affine-correct zraw -> LN -> +w -> 1x1(17->1) -> LN -> out ============
__global__ void __launch_bounds__(NTH)
k_final(const float* __restrict__ w, const float* __restrict__ cw,
        const float* __restrict__ c2w, const float* __restrict__ c3w,
        float* __restrict__ out)
{
  __shared__ float sh_z[AA*17];
  __shared__ float sh_red[18];
  __shared__ float sh_c3[17];
  __shared__ float sh_K[16];
  const int b = blockIdx.x, tid = threadIdx.x;
  if (tid < 17) sh_c3[tid] = c3w[tid];
  if (tid < 16){
    float csum[4];
    #pragma unroll
    for (int p = 0; p < 4; p++){
      float t = 0.f;
      #pragma unroll
      for (int c = 0; c < 12; c++) t += cw[p*12 + c];
      csum[p] = t;
    }
    float kk = 0.f;
    #pragma unroll
    for (int p = 0; p < 4; p++){
      const float* cb = c2w + tid*256 + p*64;
      float t = 0.f;
      for (int d = 0; d < 64; d++) t += cb[d];
      kk = fmaf(csum[p], t, kk);
    }
    sh_K[tid] = kk;
  }
  float mc, icat; finalizeStats(g_p4, b, INV_N12, mc, icat);
  __syncthreads();

  const float4* zsrc = reinterpret_cast<const float4*>(g_z + (size_t)b*AA*16);
  float sz = 0.f, qz = 0.f;
  for (int idx = tid; idx < AA*4; idx += NTH){
    float4 v = zsrc[idx];
    int a = idx >> 2, o4 = (idx & 3)*4;
    v.x = icat*(v.x - mc*sh_K[o4+0]);
    v.y = icat*(v.y - mc*sh_K[o4+1]);
    v.z = icat*(v.z - mc*sh_K[o4+2]);
    v.w = icat*(v.w - mc*sh_K[o4+3]);
    float* dst = sh_z + a*17 + o4;
    dst[0] = v.x; dst[1] = v.y; dst[2] = v.z; dst[3] = v.w;
    sz += v.x+v.y+v.z+v.w;
    qz = fmaf(v.x,v.x, fmaf(v.y,v.y, fmaf(v.z,v.z, fmaf(v.w,v.w, qz))));
  }
  blockReduce2(sz, qz, sh_red);
  const float invN4 = 1.f/(16.f*(float)AA);
  float m4 = sz*invN4;
  float i4 = rsqrtf(fmaf(-m4, m4, qz*invN4) + EPSF);

  float rv[2]; float sr = 0.f, qr = 0.f;
  #pragma unroll
  for (int j = 0; j < 2; j++){
    int a = tid + j*NTH;
    float r = sh_c3[16]*w[(size_t)b*AA + a];
    const float* zr = sh_z + a*17;
    #pragma unroll
    for (int o = 0; o < 16; o++)
      r = fmaf(sh_c3[o], (zr[o] - m4)*i4, r);
    rv[j] = r; sr += r; qr = fmaf(r, r, qr);
  }
  blockReduce2(sr, qr, sh_red);
  float m5 = sr*(1.f/(float)AA);
  float i5 = rsqrtf(fmaf(-m5, m5, qr*(1.f/(float)AA)) + EPSF);
  #pragma unroll
  for (int j = 0; j < 2; j++)
    out[(size_t)b*AA + tid + j*NTH] = (rv[j] - m5)*i5;
}

extern "C" void kernel_launch(void* const* d_in, const int* in_sizes, int n_in,
                              void* d_out, int out_size)
{
  (void)in_sizes; (void)n_in; (void)out_size;
  const float* s    = (const float*)d_in[0];
  const float* w    = (const float*)d_in[1];
  const float* d1w1 = (const float*)d_in[2];
  const float* d1w2 = (const float*)d_in[3];
  const float* d2w1 = (const float*)d_in[4];
  const float* d2w2 = (const float*)d_in[5];
  const float* d3w1 = (const float*)d_in[6];
  const float* d3w2 = (const float*)d_in[7];
  const float* cw   = (const float*)d_in[8];
  const float* c2w  = (const float*)d_in[9];
  const float* c3w  = (const float*)d_in[10];
  float* out = (float*)d_out;

  k_statsA<<<BB*CH, NTH>>>(s, d1w1);
  k_passB <<<BB*CH, NTH>>>(s, d1w1, d1w2, d2w1);
  k_passC <<<BB*CH, NTH>>>(s, d2w1, d2w2, d3w1);
  k_passD <<<BB*CH, NTH>>>(s, d3w1, d3w2, cw, c2w);
  k_final <<<BB,    NTH>>>(w, cw, c2w, c3w, out);
}

// round 7
// speedup vs baseline: 2.0051x; 2.0051x over previous
#include <cuda_runtime.h>
#include <cuda_fp16.h>
#include <math.h>

#define BB    256
#define AA    512
#define DDW   64
#define NPOS  (AA*DDW)        // 32768 positions per sample
#define NTH   256
#define CH    8               // chunks per sample
#define ROWS  (AA/CH)         // 64 rows per chunk
#define EPSF  1e-5f
#define FULLM 0xffffffffu

// Scratch: x1/x2 activations fp16 [b][a][d][c] (4 halves = uint2 per position); zraw [b][a][o]
__device__ uint2  g_x1h[(size_t)BB*NPOS];
__device__ uint2  g_x2h[(size_t)BB*NPOS];
__device__ float  g_z [(size_t)BB*AA*16];
__device__ float2 g_p1[BB*CH], g_p2[BB*CH], g_p3[BB*CH], g_p4[BB*CH];

__device__ __forceinline__ float4 f4add(float4 a, float4 b){
  return make_float4(a.x+b.x, a.y+b.y, a.z+b.z, a.w+b.w);
}
__device__ __forceinline__ float dot4(float4 w, float4 v){
  return fmaf(w.x, v.x, fmaf(w.y, v.y, fmaf(w.z, v.z, w.w*v.w)));
}
__device__ __forceinline__ float geluf(float x){
  return 0.5f * x * (1.f + erff(x * 0.70710678118654752440f));
}
// float4 <-> packed half4 (uint2)
__device__ __forceinline__ uint2 f4_to_h4(const float4& v){
  __half2 a = __floats2half2_rn(v.x, v.y);
  __half2 b = __floats2half2_rn(v.z, v.w);
  uint2 r;
  r.x = *reinterpret_cast<const unsigned int*>(&a);
  r.y = *reinterpret_cast<const unsigned int*>(&b);
  return r;
}
__device__ __forceinline__ float4 h4_to_f4(uint2 u){
  __half2 a = *reinterpret_cast<const __half2*>(&u.x);
  __half2 b = *reinterpret_cast<const __half2*>(&u.y);
  float2 f0 = __half22float2(a);
  float2 f1 = __half22float2(b);
  return make_float4(f0.x, f0.y, f1.x, f1.y);
}
__device__ __forceinline__ void loadConvW(const float* __restrict__ wp, float4 wk[3][4]){
  #pragma unroll
  for (int o = 0; o < 4; o++)
    #pragma unroll
    for (int k = 0; k < 3; k++)
      wk[k][o] = make_float4(wp[o*12 + 0 + k], wp[o*12 + 3 + k],
                             wp[o*12 + 6 + k], wp[o*12 + 9 + k]);
}
__device__ __forceinline__ float4 shflup2_4(float4 v){
  float4 r;
  r.x = __shfl_up_sync(FULLM, v.x, 2);
  r.y = __shfl_up_sync(FULLM, v.y, 2);
  r.z = __shfl_up_sync(FULLM, v.z, 2);
  r.w = __shfl_up_sync(FULLM, v.w, 2);
  return r;
}
__device__ __forceinline__ float4 shfldn2_4(float4 v){
  float4 r;
  r.x = __shfl_down_sync(FULLM, v.x, 2);
  r.y = __shfl_down_sync(FULLM, v.y, 2);
  r.z = __shfl_down_sync(FULLM, v.z, 2);
  r.w = __shfl_down_sync(FULLM, v.w, 2);
  return r;
}
__device__ __forceinline__ float4 shflsel4(float4 v, int sl){
  float4 r;
  r.x = __shfl_sync(FULLM, v.x, sl);
  r.y = __shfl_sync(FULLM, v.y, sl);
  r.z = __shfl_sync(FULLM, v.z, sl);
  r.w = __shfl_sync(FULLM, v.w, sl);
  return r;
}
// Build the 6 dilated taps for outputs d=lane and d=lane+32 from T0=v(lane), T1=v(lane+32).
struct Taps { float4 m0, p0, m1, p1; };
__device__ __forceinline__ Taps makeTaps(float4 T0, float4 T1, int lane){
  const float4 z4 = make_float4(0.f,0.f,0.f,0.f);
  Taps t;
  t.m0 = shflup2_4(T0);                 if (lane < 2)  t.m0 = z4;   // v(lane-2)
  t.p0 = shflsel4((lane < 2) ? T1 : T0, (lane+2)  & 31);            // v(lane+2)
  t.m1 = shflsel4((lane >= 30) ? T0 : T1, (lane-2) & 31);           // v(lane+30)
  t.p1 = shfldn2_4(T1);                 if (lane >= 30) t.p1 = z4;  // v(lane+34)
  return t;
}

__device__ __forceinline__ void blockReduceStore(float s, float q, float2* dst){
  #pragma unroll
  for (int off = 16; off > 0; off >>= 1){
    s += __shfl_xor_sync(FULLM, s, off);
    q += __shfl_xor_sync(FULLM, q, off);
  }
  __shared__ float red[16];
  int wp = threadIdx.x >> 5, ln = threadIdx.x & 31;
  if (ln == 0){ red[wp] = s; red[8+wp] = q; }
  __syncthreads();
  if (threadIdx.x == 0){
    float ss = 0.f, qq = 0.f;
    #pragma unroll
    for (int i = 0; i < 8; i++){ ss += red[i]; qq += red[8+i]; }
    *dst = make_float2(ss, qq);
  }
}

__device__ __forceinline__ void finalizeStats(const float2* __restrict__ part, int b,
                                              float invN, float& m, float& inv){
  float s = 0.f, q = 0.f;
  #pragma unroll
  for (int i = 0; i < CH; i++){
    float2 p = __ldg(&part[b*CH + i]);
    s += p.x; q += p.y;
  }
  m = s*invN;
  inv = rsqrtf(fmaf(-m, m, q*invN) + EPSF);
}

__device__ __forceinline__ void blockReduce2(float& s, float& q, volatile float* red){
  #pragma unroll
  for (int off = 16; off > 0; off >>= 1){
    s += __shfl_xor_sync(FULLM, s, off);
    q += __shfl_xor_sync(FULLM, q, off);
  }
  int wp = threadIdx.x >> 5, ln = threadIdx.x & 31;
  __syncthreads();
  if (ln == 0){ red[wp] = s; red[8+wp] = q; }
  __syncthreads();
  if (threadIdx.x == 0){
    float ss = 0.f, qq = 0.f;
    #pragma unroll
    for (int i = 0; i < 8; i++){ ss += red[i]; qq += red[8+i]; }
    red[16] = ss; red[17] = qq;
  }
  __syncthreads();
  s = red[16]; q = red[17];
}

#define INV_N1  (1.f/(4.f*(float)NPOS))
#define INV_N12 (1.f/(12.f*(float)NPOS))

// ============ K0: stats of y1 = conv1(s) ============
__global__ void __launch_bounds__(NTH, 3)
k_statsA(const float* __restrict__ s, const float* __restrict__ d1w1)
{
  const int b = blockIdx.x >> 3, chk = blockIdx.x & 7;
  const int lane = threadIdx.x & 31, warp = threadIdx.x >> 5;
  const float4* sb = reinterpret_cast<const float4*>(
      s + (size_t)b*NPOS*4 + (size_t)chk*ROWS*DDW*4);
  float4 wk[3][4]; loadConvW(d1w1, wk);
  float sum = 0.f, sq = 0.f;
  for (int r = 0; r < 8; ++r){
    int a = warp + 8*r;
    float4 T0 = sb[a*DDW + lane], T1 = sb[a*DDW + lane + 32];
    Taps tp = makeTaps(T0, T1, lane);
    #pragma unroll
    for (int o = 0; o < 4; o++){
      float y0 = dot4(wk[0][o], tp.m0) + dot4(wk[1][o], T0) + dot4(wk[2][o], tp.p0);
      float y1 = dot4(wk[0][o], tp.m1) + dot4(wk[1][o], T1) + dot4(wk[2][o], tp.p1);
      sum += y0 + y1; sq = fmaf(y0, y0, fmaf(y1, y1, sq));
    }
  }
  blockReduceStore(sum, sq, &g_p1[blockIdx.x]);
}

// ============ K1: x1 = gelu(pw1(LN(y1))); write x1 (fp16); stats of y2 = conv2(s+x1) ============
__global__ void __launch_bounds__(NTH, 3)
k_passB(const float* __restrict__ s, const float* __restrict__ d1w1,
        const float* __restrict__ d1w2, const float* __restrict__ d2w1)
{
  __shared__ float4 sh_w2[12];   // stats conv weights [k*4+o]
  __shared__ float4 sh_p1[4];    // pointwise weights
  const int b = blockIdx.x >> 3, chk = blockIdx.x & 7, tid = threadIdx.x;
  const int lane = tid & 31, warp = tid >> 5;
  const size_t poff = (size_t)b*NPOS + (size_t)chk*ROWS*DDW;
  const float4* sb  = reinterpret_cast<const float4*>(s + poff*4);
  uint2*        x1b = g_x1h + poff;
  if (tid < 12){
    int k = tid >> 2, o = tid & 3;
    sh_w2[tid] = make_float4(d2w1[o*12+k], d2w1[o*12+3+k], d2w1[o*12+6+k], d2w1[o*12+9+k]);
  }
  if (tid < 4) sh_p1[tid] = make_float4(d1w2[tid*4+0], d1w2[tid*4+1], d1w2[tid*4+2], d1w2[tid*4+3]);
  float4 w1k[3][4]; loadConvW(d1w1, w1k);
  float m1, i1; finalizeStats(g_p1, b, INV_N1, m1, i1);
  __syncthreads();

  float sum = 0.f, sq = 0.f;
  for (int r = 0; r < 8; ++r){
    int a = warp + 8*r;
    float4 T0 = sb[a*DDW + lane], T1 = sb[a*DDW + lane + 32];
    Taps st = makeTaps(T0, T1, lane);
    float t0[4], t1[4];
    #pragma unroll
    for (int o = 0; o < 4; o++){
      float y0 = dot4(w1k[0][o], st.m0) + dot4(w1k[1][o], T0) + dot4(w1k[2][o], st.p0);
      float y1 = dot4(w1k[0][o], st.m1) + dot4(w1k[1][o], T1) + dot4(w1k[2][o], st.p1);
      t0[o] = (y0 - m1)*i1;  t1[o] = (y1 - m1)*i1;
    }
    float4 tv0 = make_float4(t0[0], t0[1], t0[2], t0[3]);
    float4 tv1 = make_float4(t1[0], t1[1], t1[2], t1[3]);
    float4 xv0 = make_float4(geluf(dot4(sh_p1[0], tv0)), geluf(dot4(sh_p1[1], tv0)),
                             geluf(dot4(sh_p1[2], tv0)), geluf(dot4(sh_p1[3], tv0)));
    float4 xv1 = make_float4(geluf(dot4(sh_p1[0], tv1)), geluf(dot4(sh_p1[1], tv1)),
                             geluf(dot4(sh_p1[2], tv1)), geluf(dot4(sh_p1[3], tv1)));
    uint2 h0 = f4_to_h4(xv0), h1 = f4_to_h4(xv1);
    x1b[a*DDW + lane]      = h0;
    x1b[a*DDW + lane + 32] = h1;
    // use ROUNDED x1 for stats (consistency with what passC will read)
    xv0 = h4_to_f4(h0);  xv1 = h4_to_f4(h1);
    Taps xt = makeTaps(xv0, xv1, lane);
    float4 U0m = f4add(st.m0, xt.m0), U0c = f4add(T0, xv0), U0p = f4add(st.p0, xt.p0);
    float4 U1m = f4add(st.m1, xt.m1), U1c = f4add(T1, xv1), U1p = f4add(st.p1, xt.p1);
    #pragma unroll
    for (int o = 0; o < 4; o++){
      float y0 = dot4(sh_w2[o], U0m) + dot4(sh_w2[4+o], U0c) + dot4(sh_w2[8+o], U0p);
      float y1 = dot4(sh_w2[o], U1m) + dot4(sh_w2[4+o], U1c) + dot4(sh_w2[8+o], U1p);
      sum += y0 + y1; sq = fmaf(y0, y0, fmaf(y1, y1, sq));
    }
  }
  blockReduceStore(sum, sq, &g_p2[blockIdx.x]);
}

// ============ K2: x2 (fp16); stats of y3 = conv3(s+x1+x2) ============
__global__ void __launch_bounds__(NTH, 3)
k_passC(const float* __restrict__ s, const float* __restrict__ d2w1,
        const float* __restrict__ d2w2, const float* __restrict__ d3w1)
{
  __shared__ float4 sh_w3[12];
  __shared__ float4 sh_p2[4];
  const int b = blockIdx.x >> 3, chk = blockIdx.x & 7, tid = threadIdx.x;
  const int lane = tid & 31, warp = tid >> 5;
  const size_t poff = (size_t)b*NPOS + (size_t)chk*ROWS*DDW;
  const float4* sb  = reinterpret_cast<const float4*>(s + poff*4);
  const uint2*  x1b = g_x1h + poff;
  uint2*        x2b = g_x2h + poff;
  if (tid < 12){
    int k = tid >> 2, o = tid & 3;
    sh_w3[tid] = make_float4(d3w1[o*12+k], d3w1[o*12+3+k], d3w1[o*12+6+k], d3w1[o*12+9+k]);
  }
  if (tid < 4) sh_p2[tid] = make_float4(d2w2[tid*4+0], d2w2[tid*4+1], d2w2[tid*4+2], d2w2[tid*4+3]);
  float4 w2k[3][4]; loadConvW(d2w1, w2k);
  float m2, i2; finalizeStats(g_p2, b, INV_N1, m2, i2);
  __syncthreads();

  float sum = 0.f, sq = 0.f;
  for (int r = 0; r < 8; ++r){
    int a = warp + 8*r;
    float4 I0 = f4add(sb[a*DDW + lane],      h4_to_f4(x1b[a*DDW + lane]));
    float4 I1 = f4add(sb[a*DDW + lane + 32], h4_to_f4(x1b[a*DDW + lane + 32]));
    Taps it = makeTaps(I0, I1, lane);
    float t0[4], t1[4];
    #pragma unroll
    for (int o = 0; o < 4; o++){
      float y0 = dot4(w2k[0][o], it.m0) + dot4(w2k[1][o], I0) + dot4(w2k[2][o], it.p0);
      float y1 = dot4(w2k[0][o], it.m1) + dot4(w2k[1][o], I1) + dot4(w2k[2][o], it.p1);
      t0[o] = (y0 - m2)*i2;  t1[o] = (y1 - m2)*i2;
    }
    float4 tv0 = make_float4(t0[0], t0[1], t0[2], t0[3]);
    float4 tv1 = make_float4(t1[0], t1[1], t1[2], t1[3]);
    float4 xv0 = make_float4(geluf(dot4(sh_p2[0], tv0)), geluf(dot4(sh_p2[1], tv0)),
                             geluf(dot4(sh_p2[2], tv0)), geluf(dot4(sh_p2[3], tv0)));
    float4 xv1 = make_float4(geluf(dot4(sh_p2[0], tv1)), geluf(dot4(sh_p2[1], tv1)),
                             geluf(dot4(sh_p2[2], tv1)), geluf(dot4(sh_p2[3], tv1)));
    uint2 h0 = f4_to_h4(xv0), h1 = f4_to_h4(xv1);
    x2b[a*DDW + lane]      = h0;
    x2b[a*DDW + lane + 32] = h1;
    xv0 = h4_to_f4(h0);  xv1 = h4_to_f4(h1);
    Taps xt = makeTaps(xv0, xv1, lane);
    float4 U0m = f4add(it.m0, xt.m0), U0c = f4add(I0, xv0), U0p = f4add(it.p0, xt.p0);
    float4 U1m = f4add(it.m1, xt.m1), U1c = f4add(I1, xv1), U1p = f4add(it.p1, xt.p1);
    #pragma unroll
    for (int o = 0; o < 4; o++){
      float y0 = dot4(sh_w3[o], U0m) + dot4(sh_w3[4+o], U0c) + dot4(sh_w3[8+o], U0p);
      float y1 = dot4(sh_w3[o], U1m) + dot4(sh_w3[4+o], U1c) + dot4(sh_w3[8+o], U1p);
      sum += y0 + y1; sq = fmaf(y0, y0, fmaf(y1, y1, sq));
    }
  }
  blockReduceStore(sum, sq, &g_p3[blockIdx.x]);
}

// ============ K3: x3 (regs) + zraw (phase-split) + cat stats ============
__global__ void __launch_bounds__(NTH, 2)
k_passD(const float* __restrict__ s, const float* __restrict__ d3w1,
        const float* __restrict__ d3w2, const float* __restrict__ cw,
        const float* __restrict__ c2w)
{
  __shared__ float2 sh_c2[16*4*32];    // [o][p][lane] = (c2w[d=lane], c2w[d=lane+32])
  __shared__ float  sh_cw[48];         // [p*12+c]
  __shared__ float4 sh_w3[12];
  __shared__ float4 sh_p3[4];
  const int b = blockIdx.x >> 3, chk = blockIdx.x & 7, tid = threadIdx.x;
  const int lane = tid & 31, warp = tid >> 5;
  const size_t poff = (size_t)b*NPOS + (size_t)chk*ROWS*DDW;
  const float4* sb  = reinterpret_cast<const float4*>(s + poff*4);
  const uint2*  x1b = g_x1h + poff;
  const uint2*  x2b = g_x2h + poff;
  for (int k = tid; k < 2048; k += NTH){
    int l = k & 31, p = (k >> 5) & 3, o = k >> 7;
    sh_c2[k] = make_float2(c2w[o*256 + p*64 + l], c2w[o*256 + p*64 + l + 32]);
  }
  if (tid < 48) sh_cw[tid] = cw[tid];
  if (tid < 12){
    int k = tid >> 2, o = tid & 3;
    sh_w3[tid] = make_float4(d3w1[o*12+k], d3w1[o*12+3+k], d3w1[o*12+6+k], d3w1[o*12+9+k]);
  }
  if (tid < 4) sh_p3[tid] = make_float4(d3w2[tid*4+0], d3w2[tid*4+1], d3w2[tid*4+2], d3w2[tid*4+3]);
  float m3, i3; finalizeStats(g_p3, b, INV_N1, m3, i3);
  __syncthreads();

  float sum = 0.f, sq = 0.f;
  for (int g = 0; g < 2; ++g){
    float V[4][2][4];                  // [row][half][p]
    // -------- phase 1: 4 rows -> v[p] in registers --------
    #pragma unroll
    for (int r = 0; r < 4; ++r){
      int a = warp + 8*(4*g + r);
      float4 X0 = h4_to_f4(x1b[a*DDW + lane]), X1 = h4_to_f4(x1b[a*DDW + lane + 32]);
      float4 Y0 = h4_to_f4(x2b[a*DDW + lane]), Y1 = h4_to_f4(x2b[a*DDW + lane + 32]);
      float4 I0 = f4add(f4add(sb[a*DDW + lane],      X0), Y0);
      float4 I1 = f4add(f4add(sb[a*DDW + lane + 32], X1), Y1);
      Taps it = makeTaps(I0, I1, lane);
      float t0[4], t1[4];
      #pragma unroll
      for (int o = 0; o < 4; o++){
        float y0 = dot4(sh_w3[o], it.m0) + dot4(sh_w3[4+o], I0) + dot4(sh_w3[8+o], it.p0);
        float y1 = dot4(sh_w3[o], it.m1) + dot4(sh_w3[4+o], I1) + dot4(sh_w3[8+o], it.p1);
        t0[o] = (y0 - m3)*i3;  t1[o] = (y1 - m3)*i3;
      }
      float4 tv0 = make_float4(t0[0], t0[1], t0[2], t0[3]);
      float4 tv1 = make_float4(t1[0], t1[1], t1[2], t1[3]);
      float4 x30 = make_float4(geluf(dot4(sh_p3[0], tv0)), geluf(dot4(sh_p3[1], tv0)),
                               geluf(dot4(sh_p3[2], tv0)), geluf(dot4(sh_p3[3], tv0)));
      float4 x31 = make_float4(geluf(dot4(sh_p3[0], tv1)), geluf(dot4(sh_p3[1], tv1)),
                               geluf(dot4(sh_p3[2], tv1)), geluf(dot4(sh_p3[3], tv1)));
      sum += X0.x+X0.y+X0.z+X0.w + Y0.x+Y0.y+Y0.z+Y0.w + x30.x+x30.y+x30.z+x30.w;
      sum += X1.x+X1.y+X1.z+X1.w + Y1.x+Y1.y+Y1.z+Y1.w + x31.x+x31.y+x31.z+x31.w;
      sq = fmaf(X0.x,X0.x, fmaf(X0.y,X0.y, fmaf(X0.z,X0.z, fmaf(X0.w,X0.w, sq))));
      sq = fmaf(Y0.x,Y0.x, fmaf(Y0.y,Y0.y, fmaf(Y0.z,Y0.z, fmaf(Y0.w,Y0.w, sq))));
      sq = fmaf(x30.x,x30.x, fmaf(x30.y,x30.y, fmaf(x30.z,x30.z, fmaf(x30.w,x30.w, sq))));
      sq = fmaf(X1.x,X1.x, fmaf(X1.y,X1.y, fmaf(X1.z,X1.z, fmaf(X1.w,X1.w, sq))));
      sq = fmaf(Y1.x,Y1.x, fmaf(Y1.y,Y1.y, fmaf(Y1.z,Y1.z, fmaf(Y1.w,Y1.w, sq))));
      sq = fmaf(x31.x,x31.x, fmaf(x31.y,x31.y, fmaf(x31.z,x31.z, fmaf(x31.w,x31.w, sq))));
      #pragma unroll
      for (int p = 0; p < 4; p++){
        const float* cwp = sh_cw + p*12;
        float a0 = cwp[0]*X0.x + cwp[1]*X0.y + cwp[2]*X0.z + cwp[3]*X0.w;
        a0 = fmaf(cwp[4], Y0.x, fmaf(cwp[5], Y0.y, fmaf(cwp[6], Y0.z, fmaf(cwp[7], Y0.w, a0))));
        a0 = fmaf(cwp[8], x30.x, fmaf(cwp[9], x30.y, fmaf(cwp[10], x30.z, fmaf(cwp[11], x30.w, a0))));
        V[r][0][p] = a0;
        float a1 = cwp[0]*X1.x + cwp[1]*X1.y + cwp[2]*X1.z + cwp[3]*X1.w;
        a1 = fmaf(cwp[4], Y1.x, fmaf(cwp[5], Y1.y, fmaf(cwp[6], Y1.z, fmaf(cwp[7], Y1.w, a1))));
        a1 = fmaf(cwp[8], x31.x, fmaf(cwp[9], x31.y, fmaf(cwp[10], x31.z, fmaf(cwp[11], x31.w, a1))));
        V[r][1][p] = a1;
      }
    }
    // -------- phase 2: z[o] for the 4 rows; c2w read once per o --------
    #pragma unroll
    for (int o = 0; o < 16; ++o){
      float2 wv[4];
      #pragma unroll
      for (int p = 0; p < 4; p++)
        wv[p] = sh_c2[(o*4 + p)*32 + lane];
      float acc[4];
      #pragma unroll
      for (int r = 0; r < 4; ++r){
        float a0 = 0.f;
        #pragma unroll
        for (int p = 0; p < 4; p++)
          a0 = fmaf(wv[p].x, V[r][0][p], fmaf(wv[p].y, V[r][1][p], a0));
        acc[r] = a0;
      }
      const bool b4 = (lane & 16) != 0, b3 = (lane & 8) != 0;
      float s0 = b4 ? acc[2] : acc[0];
      float s1 = b4 ? acc[3] : acc[1];
      s0 += __shfl_xor_sync(FULLM, b4 ? acc[0] : acc[2], 16);
      s1 += __shfl_xor_sync(FULLM, b4 ? acc[1] : acc[3], 16);
      float sv = b3 ? s1 : s0;
      sv += __shfl_xor_sync(FULLM, b3 ? s0 : s1, 8);
      sv += __shfl_xor_sync(FULLM, sv, 4);
      sv += __shfl_xor_sync(FULLM, sv, 2);
      sv += __shfl_xor_sync(FULLM, sv, 1);
      if ((lane & 7) == 0){
        int r = ((lane >> 4) << 1) | ((lane >> 3) & 1);
        int ag = chk*ROWS + warp + 8*(4*g + r);
        g_z[((size_t)b*AA + ag)*16 + o] = sv;
      }
    }
  }
  blockReduceStore(sum, sq, &g_p4[blockIdx.x]);
}

// ============ K4: affine-correct zraw -> LN -> +w -> 1x1(17->1) -> LN -> out ============
__global__ void __launch_bounds__(NTH)
k_final(const float* __restrict__ w, const float* __restrict__ cw,
        const float* __restrict__ c2w, const float* __restrict__ c3w,
        float* __restrict__ out)
{
  __shared__ float sh_z[AA*17];
  __shared__ float sh_red[18];
  __shared__ float sh_c3[17];
  __shared__ float sh_K[16];
  const int b = blockIdx.x, tid = threadIdx.x;
  if (tid < 17) sh_c3[tid] = c3w[tid];
  if (tid < 16){
    float csum[4];
    #pragma unroll
    for (int p = 0; p < 4; p++){
      float t = 0.f;
      #pragma unroll
      for (int c = 0; c < 12; c++) t += cw[p*12 + c];
      csum[p] = t;
    }
    float kk = 0.f;
    #pragma unroll
    for (int p = 0; p < 4; p++){
      const float* cb = c2w + tid*256 + p*64;
      float t = 0.f;
      for (int d = 0; d < 64; d++) t += cb[d];
      kk = fmaf(csum[p], t, kk);
    }
    sh_K[tid] = kk;
  }
  float mc, icat; finalizeStats(g_p4, b, INV_N12, mc, icat);
  __syncthreads();

  const float4* zsrc = reinterpret_cast<const float4*>(g_z + (size_t)b*AA*16);
  float sz = 0.f, qz = 0.f;
  for (int idx = tid; idx < AA*4; idx += NTH){
    float4 v = zsrc[idx];
    int a = idx >> 2, o4 = (idx & 3)*4;
    v.x = icat*(v.x - mc*sh_K[o4+0]);
    v.y = icat*(v.y - mc*sh_K[o4+1]);
    v.z = icat*(v.z - mc*sh_K[o4+2]);
    v.w = icat*(v.w - mc*sh_K[o4+3]);
    float* dst = sh_z + a*17 + o4;
    dst[0] = v.x; dst[1] = v.y; dst[2] = v.z; dst[3] = v.w;
    sz += v.x+v.y+v.z+v.w;
    qz = fmaf(v.x,v.x, fmaf(v.y,v.y, fmaf(v.z,v.z, fmaf(v.w,v.w, qz))));
  }
  blockReduce2(sz, qz, sh_red);
  const float invN4 = 1.f/(16.f*(float)AA);
  float m4 = sz*invN4;
  float i4 = rsqrtf(fmaf(-m4, m4, qz*invN4) + EPSF);

  float rv[2]; float sr = 0.f, qr = 0.f;
  #pragma unroll
  for (int j = 0; j < 2; j++){
    int a = tid + j*NTH;
    float r = sh_c3[16]*w[(size_t)b*AA + a];
    const float* zr = sh_z + a*17;
    #pragma unroll
    for (int o = 0; o < 16; o++)
      r = fmaf(sh_c3[o], (zr[o] - m4)*i4, r);
    rv[j] = r; sr += r; qr = fmaf(r, r, qr);
  }
  blockReduce2(sr, qr, sh_red);
  float m5 = sr*(1.f/(float)AA);
  float i5 = rsqrtf(fmaf(-m5, m5, qr*(1.f/(float)AA)) + EPSF);
  #pragma unroll
  for (int j = 0; j < 2; j++)
    out[(size_t)b*AA + tid + j*NTH] = (rv[j] - m5)*i5;
}

extern "C" void kernel_launch(void* const* d_in, const int* in_sizes, int n_in,
                              void* d_out, int out_size)
{
  (void)in_sizes; (void)n_in; (void)out_size;
  const float* s    = (const float*)d_in[0];
  const float* w    = (const float*)d_in[1];
  const float* d1w1 = (const float*)d_in[2];
  const float* d1w2 = (const float*)d_in[3];
  const float* d2w1 = (const float*)d_in[4];
  const float* d2w2 = (const float*)d_in[5];
  const float* d3w1 = (const float*)d_in[6];
  const float* d3w2 = (const float*)d_in[7];
  const float* cw   = (const float*)d_in[8];
  const float* c2w  = (const float*)d_in[9];
  const float* c3w  = (const float*)d_in[10];
  float* out = (float*)d_out;

  k_statsA<<<BB*CH, NTH>>>(s, d1w1);
  k_passB <<<BB*CH, NTH>>>(s, d1w1, d1w2, d2w1);
  k_passC <<<BB*CH, NTH>>>(s, d2w1, d2w2, d3w1);
  k_passD <<<BB*CH, NTH>>>(s, d3w1, d3w2, cw, c2w);
  k_final <<<BB,    NTH>>>(w, cw, c2w, c3w, out);
}

// round 8
// speedup vs baseline: 2.1810x; 1.0877x over previous
#include <cuda_runtime.h>
#include <cuda_fp16.h>
#include <math.h>

#define BB    256
#define AA    512
#define DDW   64
#define NPOS  (AA*DDW)        // 32768 positions per sample
#define NTH   256
#define CH    8               // chunks per sample
#define ROWS  (AA/CH)         // 64 rows per chunk
#define EPSF  1e-5f
#define FULLM 0xffffffffu

// fp16 scratch: x1/x2 activations and y1/y2/y3 pre-LN conv outputs, [b][a][d][c]
__device__ uint2  g_x1h[(size_t)BB*NPOS];
__device__ uint2  g_x2h[(size_t)BB*NPOS];
__device__ uint2  g_y1h[(size_t)BB*NPOS];
__device__ uint2  g_y2h[(size_t)BB*NPOS];
__device__ uint2  g_y3h[(size_t)BB*NPOS];
__device__ float  g_z [(size_t)BB*AA*16];
__device__ float2 g_p1[BB*CH], g_p2[BB*CH], g_p3[BB*CH], g_p4[BB*CH];

__device__ __forceinline__ float4 f4add(float4 a, float4 b){
  return make_float4(a.x+b.x, a.y+b.y, a.z+b.z, a.w+b.w);
}
__device__ __forceinline__ float dot4(float4 w, float4 v){
  return fmaf(w.x, v.x, fmaf(w.y, v.y, fmaf(w.z, v.z, w.w*v.w)));
}
__device__ __forceinline__ float geluf(float x){
  return 0.5f * x * (1.f + erff(x * 0.70710678118654752440f));
}
__device__ __forceinline__ uint2 f4_to_h4(const float4& v){
  __half2 a = __floats2half2_rn(v.x, v.y);
  __half2 b = __floats2half2_rn(v.z, v.w);
  uint2 r;
  r.x = *reinterpret_cast<const unsigned int*>(&a);
  r.y = *reinterpret_cast<const unsigned int*>(&b);
  return r;
}
__device__ __forceinline__ float4 h4_to_f4(uint2 u){
  __half2 a = *reinterpret_cast<const __half2*>(&u.x);
  __half2 b = *reinterpret_cast<const __half2*>(&u.y);
  float2 f0 = __half22float2(a);
  float2 f1 = __half22float2(b);
  return make_float4(f0.x, f0.y, f1.x, f1.y);
}
__device__ __forceinline__ float4 ln4(float4 v, float m, float i){
  return make_float4((v.x-m)*i, (v.y-m)*i, (v.z-m)*i, (v.w-m)*i);
}
__device__ __forceinline__ float4 gelu_pw4(const float4* __restrict__ pw, float4 t){
  return make_float4(geluf(dot4(pw[0], t)), geluf(dot4(pw[1], t)),
                     geluf(dot4(pw[2], t)), geluf(dot4(pw[3], t)));
}
__device__ __forceinline__ void loadConvW(const float* __restrict__ wp, float4 wk[3][4]){
  #pragma unroll
  for (int o = 0; o < 4; o++)
    #pragma unroll
    for (int k = 0; k < 3; k++)
      wk[k][o] = make_float4(wp[o*12 + 0 + k], wp[o*12 + 3 + k],
                             wp[o*12 + 6 + k], wp[o*12 + 9 + k]);
}
__device__ __forceinline__ float4 shflup2_4(float4 v){
  float4 r;
  r.x = __shfl_up_sync(FULLM, v.x, 2);
  r.y = __shfl_up_sync(FULLM, v.y, 2);
  r.z = __shfl_up_sync(FULLM, v.z, 2);
  r.w = __shfl_up_sync(FULLM, v.w, 2);
  return r;
}
__device__ __forceinline__ float4 shfldn2_4(float4 v){
  float4 r;
  r.x = __shfl_down_sync(FULLM, v.x, 2);
  r.y = __shfl_down_sync(FULLM, v.y, 2);
  r.z = __shfl_down_sync(FULLM, v.z, 2);
  r.w = __shfl_down_sync(FULLM, v.w, 2);
  return r;
}
__device__ __forceinline__ float4 shflsel4(float4 v, int sl){
  float4 r;
  r.x = __shfl_sync(FULLM, v.x, sl);
  r.y = __shfl_sync(FULLM, v.y, sl);
  r.z = __shfl_sync(FULLM, v.z, sl);
  r.w = __shfl_sync(FULLM, v.w, sl);
  return r;
}
struct Taps { float4 m0, p0, m1, p1; };
__device__ __forceinline__ Taps makeTaps(float4 T0, float4 T1, int lane){
  const float4 z4 = make_float4(0.f,0.f,0.f,0.f);
  Taps t;
  t.m0 = shflup2_4(T0);                 if (lane < 2)  t.m0 = z4;   // v(lane-2)
  t.p0 = shflsel4((lane < 2) ? T1 : T0, (lane+2)  & 31);            // v(lane+2)
  t.m1 = shflsel4((lane >= 30) ? T0 : T1, (lane-2) & 31);           // v(lane+30)
  t.p1 = shfldn2_4(T1);                 if (lane >= 30) t.p1 = z4;  // v(lane+34)
  return t;
}

__device__ __forceinline__ void blockReduceStore(float s, float q, float2* dst){
  #pragma unroll
  for (int off = 16; off > 0; off >>= 1){
    s += __shfl_xor_sync(FULLM, s, off);
    q += __shfl_xor_sync(FULLM, q, off);
  }
  __shared__ float red[16];
  int wp = threadIdx.x >> 5, ln = threadIdx.x & 31;
  if (ln == 0){ red[wp] = s; red[8+wp] = q; }
  __syncthreads();
  if (threadIdx.x == 0){
    float ss = 0.f, qq = 0.f;
    #pragma unroll
    for (int i = 0; i < 8; i++){ ss += red[i]; qq += red[8+i]; }
    *dst = make_float2(ss, qq);
  }
}
__device__ __forceinline__ void finalizeStats(const float2* __restrict__ part, int b,
                                              float invN, float& m, float& inv){
  float s = 0.f, q = 0.f;
  #pragma unroll
  for (int i = 0; i < CH; i++){
    float2 p = __ldg(&part[b*CH + i]);
    s += p.x; q += p.y;
  }
  m = s*invN;
  inv = rsqrtf(fmaf(-m, m, q*invN) + EPSF);
}
__device__ __forceinline__ void blockReduce2(float& s, float& q, volatile float* red){
  #pragma unroll
  for (int off = 16; off > 0; off >>= 1){
    s += __shfl_xor_sync(FULLM, s, off);
    q += __shfl_xor_sync(FULLM, q, off);
  }
  int wp = threadIdx.x >> 5, ln = threadIdx.x & 31;
  __syncthreads();
  if (ln == 0){ red[wp] = s; red[8+wp] = q; }
  __syncthreads();
  if (threadIdx.x == 0){
    float ss = 0.f, qq = 0.f;
    #pragma unroll
    for (int i = 0; i < 8; i++){ ss += red[i]; qq += red[8+i]; }
    red[16] = ss; red[17] = qq;
  }
  __syncthreads();
  s = red[16]; q = red[17];
}

// stats helpers on float4 pairs
__device__ __forceinline__ void acc8(float4 a, float4 b, float& sum, float& sq){
  sum += a.x+a.y+a.z+a.w + b.x+b.y+b.z+b.w;
  sq = fmaf(a.x,a.x, fmaf(a.y,a.y, fmaf(a.z,a.z, fmaf(a.w,a.w, sq))));
  sq = fmaf(b.x,b.x, fmaf(b.y,b.y, fmaf(b.z,b.z, fmaf(b.w,b.w, sq))));
}

#define INV_N1  (1.f/(4.f*(float)NPOS))
#define INV_N12 (1.f/(12.f*(float)NPOS))

// ============ K0: y1 = conv1(s) -> store fp16; stats of rounded y1 ============
__global__ void __launch_bounds__(NTH, 3)
k_statsA(const float* __restrict__ s, const float* __restrict__ d1w1)
{
  const int b = blockIdx.x >> 3, chk = blockIdx.x & 7;
  const int lane = threadIdx.x & 31, warp = threadIdx.x >> 5;
  const size_t poff = (size_t)b*NPOS + (size_t)chk*ROWS*DDW;
  const float4* sb = reinterpret_cast<const float4*>(s + poff*4);
  uint2* y1b = g_y1h + poff;
  float4 wk[3][4]; loadConvW(d1w1, wk);
  float sum = 0.f, sq = 0.f;
  for (int r = 0; r < 8; ++r){
    int a = warp + 8*r;
    float4 T0 = sb[a*DDW + lane], T1 = sb[a*DDW + lane + 32];
    Taps tp = makeTaps(T0, T1, lane);
    float y0[4], y1[4];
    #pragma unroll
    for (int o = 0; o < 4; o++){
      y0[o] = dot4(wk[0][o], tp.m0) + dot4(wk[1][o], T0) + dot4(wk[2][o], tp.p0);
      y1[o] = dot4(wk[0][o], tp.m1) + dot4(wk[1][o], T1) + dot4(wk[2][o], tp.p1);
    }
    uint2 h0 = f4_to_h4(make_float4(y0[0], y0[1], y0[2], y0[3]));
    uint2 h1 = f4_to_h4(make_float4(y1[0], y1[1], y1[2], y1[3]));
    y1b[a*DDW + lane]      = h0;
    y1b[a*DDW + lane + 32] = h1;
    acc8(h4_to_f4(h0), h4_to_f4(h1), sum, sq);   // stats from ROUNDED values
  }
  blockReduceStore(sum, sq, &g_p1[blockIdx.x]);
}

// ============ K1: x1 = gelu(pw1(LN(y1h))) -> x1h; y2 = conv2(s+x1) -> y2h + stats ============
__global__ void __launch_bounds__(NTH, 3)
k_passB(const float* __restrict__ s, const float* __restrict__ d1w2,
        const float* __restrict__ d2w1)
{
  __shared__ float4 sh_w2[12];   // conv2 weights [k*4+o]
  __shared__ float4 sh_p1[4];    // pw1
  const int b = blockIdx.x >> 3, chk = blockIdx.x & 7, tid = threadIdx.x;
  const int lane = tid & 31, warp = tid >> 5;
  const size_t poff = (size_t)b*NPOS + (size_t)chk*ROWS*DDW;
  const float4* sb  = reinterpret_cast<const float4*>(s + poff*4);
  const uint2*  y1b = g_y1h + poff;
  uint2*        x1b = g_x1h + poff;
  uint2*        y2b = g_y2h + poff;
  if (tid < 12){
    int k = tid >> 2, o = tid & 3;
    sh_w2[tid] = make_float4(d2w1[o*12+k], d2w1[o*12+3+k], d2w1[o*12+6+k], d2w1[o*12+9+k]);
  }
  if (tid < 4) sh_p1[tid] = make_float4(d1w2[tid*4+0], d1w2[tid*4+1], d1w2[tid*4+2], d1w2[tid*4+3]);
  float m1, i1; finalizeStats(g_p1, b, INV_N1, m1, i1);
  __syncthreads();

  float sum = 0.f, sq = 0.f;
  for (int r = 0; r < 8; ++r){
    int a = warp + 8*r;
    // apply: x1 from stored y1 (no conv recompute)
    float4 xv0 = gelu_pw4(sh_p1, ln4(h4_to_f4(y1b[a*DDW + lane]),      m1, i1));
    float4 xv1 = gelu_pw4(sh_p1, ln4(h4_to_f4(y1b[a*DDW + lane + 32]), m1, i1));
    uint2 hx0 = f4_to_h4(xv0), hx1 = f4_to_h4(xv1);
    x1b[a*DDW + lane]      = hx0;
    x1b[a*DDW + lane + 32] = hx1;
    xv0 = h4_to_f4(hx0);  xv1 = h4_to_f4(hx1);   // rounded, consistent with readers
    // fused y2 = conv2(s + x1): sum first, tap once
    float4 I0 = f4add(sb[a*DDW + lane],      xv0);
    float4 I1 = f4add(sb[a*DDW + lane + 32], xv1);
    Taps it = makeTaps(I0, I1, lane);
    float y0[4], y1[4];
    #pragma unroll
    for (int o = 0; o < 4; o++){
      y0[o] = dot4(sh_w2[o], it.m0) + dot4(sh_w2[4+o], I0) + dot4(sh_w2[8+o], it.p0);
      y1[o] = dot4(sh_w2[o], it.m1) + dot4(sh_w2[4+o], I1) + dot4(sh_w2[8+o], it.p1);
    }
    uint2 h0 = f4_to_h4(make_float4(y0[0], y0[1], y0[2], y0[3]));
    uint2 h1 = f4_to_h4(make_float4(y1[0], y1[1], y1[2], y1[3]));
    y2b[a*DDW + lane]      = h0;
    y2b[a*DDW + lane + 32] = h1;
    acc8(h4_to_f4(h0), h4_to_f4(h1), sum, sq);
  }
  blockReduceStore(sum, sq, &g_p2[blockIdx.x]);
}

// ============ K2: x2 = gelu(pw2(LN(y2h))) -> x2h; y3 = conv3(s+x1+x2) -> y3h + stats ============
__global__ void __launch_bounds__(NTH, 3)
k_passC(const float* __restrict__ s, const float* __restrict__ d2w2,
        const float* __restrict__ d3w1)
{
  __shared__ float4 sh_w3[12];
  __shared__ float4 sh_p2[4];
  const int b = blockIdx.x >> 3, chk = blockIdx.x & 7, tid = threadIdx.x;
  const int lane = tid & 31, warp = tid >> 5;
  const size_t poff = (size_t)b*NPOS + (size_t)chk*ROWS*DDW;
  const float4* sb  = reinterpret_cast<const float4*>(s + poff*4);
  const uint2*  x1b = g_x1h + poff;
  const uint2*  y2b = g_y2h + poff;
  uint2*        x2b = g_x2h + poff;
  uint2*        y3b = g_y3h + poff;
  if (tid < 12){
    int k = tid >> 2, o = tid & 3;
    sh_w3[tid] = make_float4(d3w1[o*12+k], d3w1[o*12+3+k], d3w1[o*12+6+k], d3w1[o*12+9+k]);
  }
  if (tid < 4) sh_p2[tid] = make_float4(d2w2[tid*4+0], d2w2[tid*4+1], d2w2[tid*4+2], d2w2[tid*4+3]);
  float m2, i2; finalizeStats(g_p2, b, INV_N1, m2, i2);
  __syncthreads();

  float sum = 0.f, sq = 0.f;
  for (int r = 0; r < 8; ++r){
    int a = warp + 8*r;
    float4 xv0 = gelu_pw4(sh_p2, ln4(h4_to_f4(y2b[a*DDW + lane]),      m2, i2));
    float4 xv1 = gelu_pw4(sh_p2, ln4(h4_to_f4(y2b[a*DDW + lane + 32]), m2, i2));
    uint2 hx0 = f4_to_h4(xv0), hx1 = f4_to_h4(xv1);
    x2b[a*DDW + lane]      = hx0;
    x2b[a*DDW + lane + 32] = hx1;
    xv0 = h4_to_f4(hx0);  xv1 = h4_to_f4(hx1);
    float4 I0 = f4add(f4add(sb[a*DDW + lane],      h4_to_f4(x1b[a*DDW + lane])),      xv0);
    float4 I1 = f4add(f4add(sb[a*DDW + lane + 32], h4_to_f4(x1b[a*DDW + lane + 32])), xv1);
    Taps it = makeTaps(I0, I1, lane);
    float y0[4], y1[4];
    #pragma unroll
    for (int o = 0; o < 4; o++){
      y0[o] = dot4(sh_w3[o], it.m0) + dot4(sh_w3[4+o], I0) + dot4(sh_w3[8+o], it.p0);
      y1[o] = dot4(sh_w3[o], it.m1) + dot4(sh_w3[4+o], I1) + dot4(sh_w3[8+o], it.p1);
    }
    uint2 h0 = f4_to_h4(make_float4(y0[0], y0[1], y0[2], y0[3]));
    uint2 h1 = f4_to_h4(make_float4(y1[0], y1[1], y1[2], y1[3]));
    y3b[a*DDW + lane]      = h0;
    y3b[a*DDW + lane + 32] = h1;
    acc8(h4_to_f4(h0), h4_to_f4(h1), sum, sq);
  }
  blockReduceStore(sum, sq, &g_p3[blockIdx.x]);
}

// ============ K3: x3 from y3h (no conv, no taps) + zraw + cat stats ============
__global__ void __launch_bounds__(NTH, 2)
k_passD(const float* __restrict__ d3w2, const float* __restrict__ cw,
        const float* __restrict__ c2w)
{
  __shared__ float2 sh_c2[16*4*32];    // [o][p][lane] = (c2w[d=lane], c2w[d=lane+32])
  __shared__ float  sh_cw[48];         // [p*12+c]
  __shared__ float4 sh_p3[4];
  const int b = blockIdx.x >> 3, chk = blockIdx.x & 7, tid = threadIdx.x;
  const int lane = tid & 31, warp = tid >> 5;
  const size_t poff = (size_t)b*NPOS + (size_t)chk*ROWS*DDW;
  const uint2*  x1b = g_x1h + poff;
  const uint2*  x2b = g_x2h + poff;
  const uint2*  y3b = g_y3h + poff;
  for (int k = tid; k < 2048; k += NTH){
    int l = k & 31, p = (k >> 5) & 3, o = k >> 7;
    sh_c2[k] = make_float2(c2w[o*256 + p*64 + l], c2w[o*256 + p*64 + l + 32]);
  }
  if (tid < 48) sh_cw[tid] = cw[tid];
  if (tid < 4) sh_p3[tid] = make_float4(d3w2[tid*4+0], d3w2[tid*4+1], d3w2[tid*4+2], d3w2[tid*4+3]);
  float m3, i3; finalizeStats(g_p3, b, INV_N1, m3, i3);
  __syncthreads();

  float sum = 0.f, sq = 0.f;
  for (int g = 0; g < 2; ++g){
    float V[4][2][4];                  // [row][half][p]
    // -------- phase 1: 4 rows -> v[p] in registers (pure pointwise now) --------
    #pragma unroll
    for (int r = 0; r < 4; ++r){
      int a = warp + 8*(4*g + r);
      float4 X0 = h4_to_f4(x1b[a*DDW + lane]), X1 = h4_to_f4(x1b[a*DDW + lane + 32]);
      float4 Y0 = h4_to_f4(x2b[a*DDW + lane]), Y1 = h4_to_f4(x2b[a*DDW + lane + 32]);
      float4 x30 = gelu_pw4(sh_p3, ln4(h4_to_f4(y3b[a*DDW + lane]),      m3, i3));
      float4 x31 = gelu_pw4(sh_p3, ln4(h4_to_f4(y3b[a*DDW + lane + 32]), m3, i3));
      acc8(X0, X1, sum, sq);
      acc8(Y0, Y1, sum, sq);
      acc8(x30, x31, sum, sq);
      #pragma unroll
      for (int p = 0; p < 4; p++){
        const float* cwp = sh_cw + p*12;
        float a0 = cwp[0]*X0.x + cwp[1]*X0.y + cwp[2]*X0.z + cwp[3]*X0.w;
        a0 = fmaf(cwp[4], Y0.x, fmaf(cwp[5], Y0.y, fmaf(cwp[6], Y0.z, fmaf(cwp[7], Y0.w, a0))));
        a0 = fmaf(cwp[8], x30.x, fmaf(cwp[9], x30.y, fmaf(cwp[10], x30.z, fmaf(cwp[11], x30.w, a0))));
        V[r][0][p] = a0;
        float a1 = cwp[0]*X1.x + cwp[1]*X1.y + cwp[2]*X1.z + cwp[3]*X1.w;
        a1 = fmaf(cwp[4], Y1.x, fmaf(cwp[5], Y1.y, fmaf(cwp[6], Y1.z, fmaf(cwp[7], Y1.w, a1))));
        a1 = fmaf(cwp[8], x31.x, fmaf(cwp[9], x31.y, fmaf(cwp[10], x31.z, fmaf(cwp[11], x31.w, a1))));
        V[r][1][p] = a1;
      }
    }
    // -------- phase 2: z[o] for the 4 rows; c2w read once per o --------
    #pragma unroll
    for (int o = 0; o < 16; ++o){
      float2 wv[4];
      #pragma unroll
      for (int p = 0; p < 4; p++)
        wv[p] = sh_c2[(o*4 + p)*32 + lane];
      float acc[4];
      #pragma unroll
      for (int r = 0; r < 4; ++r){
        float a0 = 0.f;
        #pragma unroll
        for (int p = 0; p < 4; p++)
          a0 = fmaf(wv[p].x, V[r][0][p], fmaf(wv[p].y, V[r][1][p], a0));
        acc[r] = a0;
      }
      const bool b4 = (lane & 16) != 0, b3 = (lane & 8) != 0;
      float s0 = b4 ? acc[2] : acc[0];
      float s1 = b4 ? acc[3] : acc[1];
      s0 += __shfl_xor_sync(FULLM, b4 ? acc[0] : acc[2], 16);
      s1 += __shfl_xor_sync(FULLM, b4 ? acc[1] : acc[3], 16);
      float sv = b3 ? s1 : s0;
      sv += __shfl_xor_sync(FULLM, b3 ? s0 : s1, 8);
      sv += __shfl_xor_sync(FULLM, sv, 4);
      sv += __shfl_xor_sync(FULLM, sv, 2);
      sv += __shfl_xor_sync(FULLM, sv, 1);
      if ((lane & 7) == 0){
        int r = ((lane >> 4) << 1) | ((lane >> 3) & 1);
        int ag = chk*ROWS + warp + 8*(4*g + r);
        g_z[((size_t)b*AA + ag)*16 + o] = sv;
      }
    }
  }
  blockReduceStore(sum, sq, &g_p4[blockIdx.x]);
}

// ============ K4: affine-correct zraw -> LN -> +w -> 1x1(17->1) -> LN -> out ============
__global__ void __launch_bounds__(NTH)
k_final(const float* __restrict__ w, const float* __restrict__ cw,
        const float* __restrict__ c2w, const float* __restrict__ c3w,
        float* __restrict__ out)
{
  __shared__ float sh_z[AA*17];
  __shared__ float sh_red[18];
  __shared__ float sh_c3[17];
  __shared__ float sh_K[16];
  const int b = blockIdx.x, tid = threadIdx.x;
  if (tid < 17) sh_c3[tid] = c3w[tid];
  if (tid < 16){
    float csum[4];
    #pragma unroll
    for (int p = 0; p < 4; p++){
      float t = 0.f;
      #pragma unroll
      for (int c = 0; c < 12; c++) t += cw[p*12 + c];
      csum[p] = t;
    }
    float kk = 0.f;
    #pragma unroll
    for (int p = 0; p < 4; p++){
      const float* cb = c2w + tid*256 + p*64;
      float t = 0.f;
      for (int d = 0; d < 64; d++) t += cb[d];
      kk = fmaf(csum[p], t, kk);
    }
    sh_K[tid] = kk;
  }
  float mc, icat; finalizeStats(g_p4, b, INV_N12, mc, icat);
  __syncthreads();

  const float4* zsrc = reinterpret_cast<const float4*>(g_z + (size_t)b*AA*16);
  float sz = 0.f, qz = 0.f;
  for (int idx = tid; idx < AA*4; idx += NTH){
    float4 v = zsrc[idx];
    int a = idx >> 2, o4 = (idx & 3)*4;
    v.x = icat*(v.x - mc*sh_K[o4+0]);
    v.y = icat*(v.y - mc*sh_K[o4+1]);
    v.z = icat*(v.z - mc*sh_K[o4+2]);
    v.w = icat*(v.w - mc*sh_K[o4+3]);
    float* dst = sh_z + a*17 + o4;
    dst[0] = v.x; dst[1] = v.y; dst[2] = v.z; dst[3] = v.w;
    sz += v.x+v.y+v.z+v.w;
    qz = fmaf(v.x,v.x, fmaf(v.y,v.y, fmaf(v.z,v.z, fmaf(v.w,v.w, qz))));
  }
  blockReduce2(sz, qz, sh_red);
  const float invN4 = 1.f/(16.f*(float)AA);
  float m4 = sz*invN4;
  float i4 = rsqrtf(fmaf(-m4, m4, qz*invN4) + EPSF);

  float rv[2]; float sr = 0.f, qr = 0.f;
  #pragma unroll
  for (int j = 0; j < 2; j++){
    int a = tid + j*NTH;
    float r = sh_c3[16]*w[(size_t)b*AA + a];
    const float* zr = sh_z + a*17;
    #pragma unroll
    for (int o = 0; o < 16; o++)
      r = fmaf(sh_c3[o], (zr[o] - m4)*i4, r);
    rv[j] = r; sr += r; qr = fmaf(r, r, qr);
  }
  blockReduce2(sr, qr, sh_red);
  float m5 = sr*(1.f/(float)AA);
  float i5 = rsqrtf(fmaf(-m5, m5, qr*(1.f/(float)AA)) + EPSF);
  #pragma unroll
  for (int j = 0; j < 2; j++)
    out[(size_t)b*AA + tid + j*NTH] = (rv[j] - m5)*i5;
}

extern "C" void kernel_launch(void* const* d_in, const int* in_sizes, int n_in,
                              void* d_out, int out_size)
{
  (void)in_sizes; (void)n_in; (void)out_size;
  const float* s    = (const float*)d_in[0];
  const float* w    = (const float*)d_in[1];
  const float* d1w1 = (const float*)d_in[2];
  const float* d1w2 = (const float*)d_in[3];
  const float* d2w1 = (const float*)d_in[4];
  const float* d2w2 = (const float*)d_in[5];
  const float* d3w1 = (const float*)d_in[6];
  const float* d3w2 = (const float*)d_in[7];
  const float* cw   = (const float*)d_in[8];
  const float* c2w  = (const float*)d_in[9];
  const float* c3w  = (const float*)d_in[10];
  float* out = (float*)d_out;

  k_statsA<<<BB*CH, NTH>>>(s, d1w1);
  k_passB <<<BB*CH, NTH>>>(s, d1w2, d2w1);
  k_passC <<<BB*CH, NTH>>>(s, d2w2, d3w1);
  k_passD <<<BB*CH, NTH>>>(d3w2, cw, c2w);
  k_final <<<BB,    NTH>>>(w, cw, c2w, c3w, out);
}